// round 6
// baseline (speedup 1.0000x reference)
#include <cuda_runtime.h>
#include <cuda_bf16.h>
#include <math.h>

#define N_NODES 50000
#define N_EDGES 800000
#define D 128
#define D4 (D / 4)
#define LN_EPS 1e-12f
#define TILE_N 64
#define SCAN_B 256
#define N_SB ((N_NODES + SCAN_B - 1) / SCAN_B)   // 196

// ---------------- scratch (no allocation allowed) ----------------
__device__ __align__(16) float g_h0[N_NODES * D];
__device__ __align__(16) float g_h1[N_NODES * D];
__device__ __align__(16) float g_WT[4][D * D];   // Wl0^T, Wr0^T, Wl1^T, Wr1^T (as WT[k][c])
__device__ int   g_deg[N_NODES];
__device__ int   g_row[N_NODES + 1];
__device__ int   g_cursor[N_NODES];
__device__ float g_invd[N_NODES];
__device__ int   g_perm[N_EDGES];
__device__ int   g_bsum[N_SB];
__device__ int   g_boff[N_SB];

// ---------------- kernels ----------------

// Transpose a DxD matrix: wt[k*D + c] = w[c*D + k]. 4 matrices.
__global__ void transpose_w_kernel(const float* __restrict__ w0,
                                   const float* __restrict__ w1,
                                   const float* __restrict__ w2,
                                   const float* __restrict__ w3,
                                   float* __restrict__ wt) {
    int i = blockIdx.x * blockDim.x + threadIdx.x;   // 0 .. 4*D*D-1
    if (i >= 4 * D * D) return;
    int m = i / (D * D);
    int r = (i % (D * D)) / D;   // source row c
    int k = i % D;               // source col k
    const float* w = (m == 0) ? w0 : (m == 1) ? w1 : (m == 2) ? w2 : w3;
    wt[m * D * D + k * D + r] = w[r * D + k];
}

// Sum of 4 embedding lookups + LayerNorm. One block (128 threads) per node.
__global__ void embed_ln_kernel(const int* __restrict__ x,
                                const float* __restrict__ syn,
                                const float* __restrict__ lem,
                                const float* __restrict__ pos,
                                const float* __restrict__ sen,
                                const float* __restrict__ g,
                                const float* __restrict__ b,
                                float* __restrict__ out) {
    int node = blockIdx.x;
    int t = threadIdx.x;
    int4 xi = ((const int4*)x)[node];  // cols 0..3
    float f = syn[(long)xi.x * D + t] + pos[(long)xi.y * D + t] +
              sen[(long)xi.z * D + t] + lem[(long)xi.w * D + t];

    __shared__ float red1[4];
    __shared__ float red2[4];
    int w = t >> 5, l = t & 31;

    float s = f;
    #pragma unroll
    for (int o = 16; o > 0; o >>= 1) s += __shfl_xor_sync(0xffffffffu, s, o);
    if (l == 0) red1[w] = s;
    __syncthreads();
    float mu = (red1[0] + red1[1] + red1[2] + red1[3]) * (1.0f / D);

    float d = f - mu;
    float v = d * d;
    #pragma unroll
    for (int o = 16; o > 0; o >>= 1) v += __shfl_xor_sync(0xffffffffu, v, o);
    if (l == 0) red2[w] = v;
    __syncthreads();
    float var = (red2[0] + red2[1] + red2[2] + red2[3]) * (1.0f / D);

    out[node * D + t] = d * rsqrtf(var + LN_EPS) * g[t] + b[t];
}

// In-degree count (int).
__global__ void count_kernel(const int* __restrict__ ei, int* __restrict__ deg) {
    int e = blockIdx.x * blockDim.x + threadIdx.x;
    if (e < N_EDGES) atomicAdd(&deg[ei[N_EDGES + e]], 1);
}

// Phase 1: per-block sum of 256 degrees.
__global__ __launch_bounds__(SCAN_B)
void block_sum_kernel(const int* __restrict__ deg, int* __restrict__ bsum) {
    __shared__ int ws[8];
    int node = blockIdx.x * SCAN_B + threadIdx.x;
    int d = (node < N_NODES) ? deg[node] : 0;
    int s = d;
    #pragma unroll
    for (int o = 16; o > 0; o >>= 1) s += __shfl_xor_sync(0xffffffffu, s, o);
    int w = threadIdx.x >> 5, l = threadIdx.x & 31;
    if (l == 0) ws[w] = s;
    __syncthreads();
    if (threadIdx.x == 0) {
        int tot = 0;
        #pragma unroll
        for (int i = 0; i < 8; i++) tot += ws[i];
        bsum[blockIdx.x] = tot;
    }
}

// Phase 2: exclusive scan of N_SB block sums. One block of 256 threads.
__global__ __launch_bounds__(256)
void scan_bsums_kernel(const int* __restrict__ bsum, int* __restrict__ boff) {
    __shared__ int sm[256];
    int t = threadIdx.x;
    int v = (t < N_SB) ? bsum[t] : 0;
    sm[t] = v;
    __syncthreads();
    for (int o = 1; o < 256; o <<= 1) {
        int u = (t >= o) ? sm[t - o] : 0;
        __syncthreads();
        sm[t] += u;
        __syncthreads();
    }
    if (t < N_SB) boff[t] = sm[t] - v;  // exclusive
}

// Phase 3: per-block exclusive scan + base offset -> row, cursor, invd.
__global__ __launch_bounds__(SCAN_B)
void expand_kernel(const int* __restrict__ deg,
                   const int* __restrict__ boff,
                   int* __restrict__ row,
                   int* __restrict__ cursor,
                   float* __restrict__ invd) {
    __shared__ int ws[8];
    __shared__ int wo[8];
    int t = threadIdx.x;
    int node = blockIdx.x * SCAN_B + t;
    int d = (node < N_NODES) ? deg[node] : 0;

    int incl = d;
    int l = t & 31, w = t >> 5;
    #pragma unroll
    for (int o = 1; o < 32; o <<= 1) {
        int u = __shfl_up_sync(0xffffffffu, incl, o);
        if (l >= o) incl += u;
    }
    if (l == 31) ws[w] = incl;
    __syncthreads();
    if (t == 0) {
        int run = 0;
        #pragma unroll
        for (int i = 0; i < 8; i++) { wo[i] = run; run += ws[i]; }
    }
    __syncthreads();

    if (node < N_NODES) {
        int excl = boff[blockIdx.x] + wo[w] + incl - d;
        row[node] = excl;
        cursor[node] = excl;
        invd[node] = 1.0f / fmaxf((float)d, 1.0f);
    }
    if (node == 0) row[N_NODES] = N_EDGES;
}

// Fill permutation: for each edge, place src into dst's CSR segment.
__global__ void build_perm_kernel(const int* __restrict__ ei,
                                  int* __restrict__ cursor,
                                  int* __restrict__ perm) {
    int e = blockIdx.x * blockDim.x + threadIdx.x;
    if (e >= N_EDGES) return;
    int dst = ei[N_EDGES + e];
    int pos = atomicAdd(&cursor[dst], 1);
    perm[pos] = ei[e];
}

// Fused SAGE layer: per-block CSR mean-gather into smem, then dual GEMM.
// out[n][c] = act( mean_nbr(h)[n] . Wl[c] + bl[c] + h[n] . Wr[c] )
// Weights TRANSPOSED: WT[k][c]. Block: 64 nodes x 128 cols, 256 threads.
__global__ __launch_bounds__(256)
void sage_layer_kernel(const float* __restrict__ h,
                       const int* __restrict__ row,
                       const int* __restrict__ perm,
                       const float* __restrict__ invd,
                       const float* __restrict__ WTl,
                       const float* __restrict__ bl,
                       const float* __restrict__ WTr,
                       float* __restrict__ out,
                       int relu) {
    extern __shared__ float smem[];
    float* sa = smem;               // [TILE_N][D]  gathered means
    float* sh = smem + TILE_N * D;  // [TILE_N][D]  self features

    int n0 = blockIdx.x * TILE_N;
    int t = threadIdx.x;
    int lane = t & 31;
    int wid = t >> 5;

    // Phase A: stage self-features tile (coalesced)
    for (int i = t; i < TILE_N * D4; i += 256) {
        int r = i / D4;
        int c4 = i % D4;
        int node = n0 + r;
        float4 hv = make_float4(0.f, 0.f, 0.f, 0.f);
        if (node < N_NODES) hv = ((const float4*)h)[node * D4 + c4];
        ((float4*)&sh[r * D])[c4] = hv;
    }

    // Phase B: CSR mean-gather. Warp wid handles nodes wid, wid+8, ...
    for (int r = wid; r < TILE_N; r += 8) {
        int node = n0 + r;
        float4 acc = make_float4(0.f, 0.f, 0.f, 0.f);
        if (node < N_NODES) {
            int beg = row[node];
            int end = row[node + 1];
            for (int j = beg; j < end; j += 32) {
                int nj = min(32, end - j);
                int s = (j + lane < end) ? __ldg(&perm[j + lane]) : 0;
                int k = 0;
                for (; k + 8 <= nj; k += 8) {
                    int s0 = __shfl_sync(0xffffffffu, s, k);
                    int s1 = __shfl_sync(0xffffffffu, s, k + 1);
                    int s2 = __shfl_sync(0xffffffffu, s, k + 2);
                    int s3 = __shfl_sync(0xffffffffu, s, k + 3);
                    int s4 = __shfl_sync(0xffffffffu, s, k + 4);
                    int s5 = __shfl_sync(0xffffffffu, s, k + 5);
                    int s6 = __shfl_sync(0xffffffffu, s, k + 6);
                    int s7 = __shfl_sync(0xffffffffu, s, k + 7);
                    float4 v0 = ((const float4*)h)[s0 * D4 + lane];
                    float4 v1 = ((const float4*)h)[s1 * D4 + lane];
                    float4 v2 = ((const float4*)h)[s2 * D4 + lane];
                    float4 v3 = ((const float4*)h)[s3 * D4 + lane];
                    float4 v4 = ((const float4*)h)[s4 * D4 + lane];
                    float4 v5 = ((const float4*)h)[s5 * D4 + lane];
                    float4 v6 = ((const float4*)h)[s6 * D4 + lane];
                    float4 v7 = ((const float4*)h)[s7 * D4 + lane];
                    acc.x += (v0.x + v1.x) + (v2.x + v3.x) + (v4.x + v5.x) + (v6.x + v7.x);
                    acc.y += (v0.y + v1.y) + (v2.y + v3.y) + (v4.y + v5.y) + (v6.y + v7.y);
                    acc.z += (v0.z + v1.z) + (v2.z + v3.z) + (v4.z + v5.z) + (v6.z + v7.z);
                    acc.w += (v0.w + v1.w) + (v2.w + v3.w) + (v4.w + v5.w) + (v6.w + v7.w);
                }
                for (; k < nj; k++) {
                    int sk = __shfl_sync(0xffffffffu, s, k);
                    float4 v = ((const float4*)h)[sk * D4 + lane];
                    acc.x += v.x; acc.y += v.y; acc.z += v.z; acc.w += v.w;
                }
            }
            float iv = invd[node];
            acc.x *= iv; acc.y *= iv; acc.z *= iv; acc.w *= iv;
        }
        ((float4*)&sa[r * D])[lane] = acc;
    }
    __syncthreads();

    // Phase C: dual GEMM. Thread tile 8 nodes x 4 cols.
    int cx = lane * 4;       // column base (0..124)
    int ny = wid * 8;        // node base within tile (0..56)

    float acc[8][4];
    #pragma unroll
    for (int n = 0; n < 8; n++)
        #pragma unroll
        for (int j = 0; j < 4; j++) acc[n][j] = 0.f;

    for (int k = 0; k < D; k += 4) {
        float4 wl[4], wr[4];
        #pragma unroll
        for (int kk = 0; kk < 4; kk++) {
            wl[kk] = __ldg((const float4*)&WTl[(k + kk) * D + cx]);
            wr[kk] = __ldg((const float4*)&WTr[(k + kk) * D + cx]);
        }
        #pragma unroll
        for (int n = 0; n < 8; n++) {
            float4 a4 = *(const float4*)&sa[(ny + n) * D + k];  // broadcast LDS
            float4 h4 = *(const float4*)&sh[(ny + n) * D + k];
            #pragma unroll
            for (int j = 0; j < 4; j++) {
                float r = acc[n][j];
                r = fmaf(a4.x, ((const float*)&wl[0])[j], r);
                r = fmaf(a4.y, ((const float*)&wl[1])[j], r);
                r = fmaf(a4.z, ((const float*)&wl[2])[j], r);
                r = fmaf(a4.w, ((const float*)&wl[3])[j], r);
                r = fmaf(h4.x, ((const float*)&wr[0])[j], r);
                r = fmaf(h4.y, ((const float*)&wr[1])[j], r);
                r = fmaf(h4.z, ((const float*)&wr[2])[j], r);
                r = fmaf(h4.w, ((const float*)&wr[3])[j], r);
                acc[n][j] = r;
            }
        }
    }

    float4 bias = __ldg((const float4*)&bl[cx]);
    #pragma unroll
    for (int n = 0; n < 8; n++) {
        int node = n0 + ny + n;
        if (node < N_NODES) {
            float4 o;
            o.x = acc[n][0] + bias.x;
            o.y = acc[n][1] + bias.y;
            o.z = acc[n][2] + bias.z;
            o.w = acc[n][3] + bias.w;
            if (relu) {
                o.x = fmaxf(o.x, 0.f);
                o.y = fmaxf(o.y, 0.f);
                o.z = fmaxf(o.z, 0.f);
                o.w = fmaxf(o.w, 0.f);
            }
            ((float4*)out)[node * D4 + (cx >> 2)] = o;
        }
    }
}

// ---------------- launch ----------------

extern "C" void kernel_launch(void* const* d_in, const int* in_sizes, int n_in,
                              void* d_out, int out_size) {
    const int*   x    = (const int*)d_in[0];
    const int*   ei   = (const int*)d_in[1];
    const float* syn  = (const float*)d_in[2];
    const float* lem  = (const float*)d_in[3];
    const float* pos  = (const float*)d_in[4];
    const float* sen  = (const float*)d_in[5];
    const float* ln_g = (const float*)d_in[6];
    const float* ln_b = (const float*)d_in[7];
    const float* Wl0  = (const float*)d_in[8];
    const float* bl0  = (const float*)d_in[9];
    const float* Wr0  = (const float*)d_in[10];
    const float* Wl1  = (const float*)d_in[11];
    const float* bl1  = (const float*)d_in[12];
    const float* Wr1  = (const float*)d_in[13];
    float* out = (float*)d_out;

    float *h0, *h1, *invd, *wt;
    int *deg, *row, *cursor, *perm, *bsum, *boff;
    cudaGetSymbolAddress((void**)&h0,     g_h0);
    cudaGetSymbolAddress((void**)&h1,     g_h1);
    cudaGetSymbolAddress((void**)&deg,    g_deg);
    cudaGetSymbolAddress((void**)&row,    g_row);
    cudaGetSymbolAddress((void**)&cursor, g_cursor);
    cudaGetSymbolAddress((void**)&invd,   g_invd);
    cudaGetSymbolAddress((void**)&perm,   g_perm);
    cudaGetSymbolAddress((void**)&bsum,   g_bsum);
    cudaGetSymbolAddress((void**)&boff,   g_boff);
    cudaGetSymbolAddress((void**)&wt,     g_WT);

    static const int smem_bytes = TILE_N * D * 4 * 2;  // 64 KB
    cudaFuncSetAttribute(sage_layer_kernel,
                         cudaFuncAttributeMaxDynamicSharedMemorySize, smem_bytes);

    const int eblocks = (N_EDGES + 255) / 256;
    const int layer_blocks = (N_NODES + TILE_N - 1) / TILE_N;

    // 0. transpose weights (WT[k][c])
    transpose_w_kernel<<<(4 * D * D + 255) / 256, 256>>>(Wl0, Wr0, Wl1, Wr1, wt);

    // 1. embeddings + LayerNorm -> h0
    embed_ln_kernel<<<N_NODES, 128>>>(x, syn, lem, pos, sen, ln_g, ln_b, h0);

    // 2. CSR build (parallel scan)
    cudaMemsetAsync(deg, 0, N_NODES * sizeof(int));
    count_kernel<<<eblocks, 256>>>(ei, deg);
    block_sum_kernel<<<N_SB, SCAN_B>>>(deg, bsum);
    scan_bsums_kernel<<<1, 256>>>(bsum, boff);
    expand_kernel<<<N_SB, SCAN_B>>>(deg, boff, row, cursor, invd);
    build_perm_kernel<<<eblocks, 256>>>(ei, cursor, perm);

    // 3. layer 0 (fused gather + combine)
    sage_layer_kernel<<<layer_blocks, 256, smem_bytes>>>(
        h0, row, perm, invd, wt + 0 * D * D, bl0, wt + 1 * D * D, h1, 1);

    // 4. layer 1
    sage_layer_kernel<<<layer_blocks, 256, smem_bytes>>>(
        h1, row, perm, invd, wt + 2 * D * D, bl1, wt + 3 * D * D, out, 0);
}

// round 7
// speedup vs baseline: 1.0366x; 1.0366x over previous
#include <cuda_runtime.h>
#include <cuda_bf16.h>
#include <math.h>

#define N_NODES 50000
#define N_EDGES 800000
#define D 128
#define D4 (D / 4)
#define LN_EPS 1e-12f
#define TILE_N 64
#define SCAN_B 256
#define N_SB ((N_NODES + SCAN_B - 1) / SCAN_B)   // 196

typedef unsigned long long ull;

// ---------------- scratch (no allocation allowed) ----------------
__device__ __align__(16) float g_h0[N_NODES * D];
__device__ __align__(16) float g_h1[N_NODES * D];
__device__ __align__(16) float g_agg[N_NODES * D];
__device__ __align__(16) float g_WT[4][D * D];   // Wl0^T, Wr0^T, Wl1^T, Wr1^T (as WT[k][c])
__device__ int   g_deg[N_NODES];
__device__ int   g_row[N_NODES + 1];
__device__ int   g_cursor[N_NODES];
__device__ float g_invd[N_NODES];
__device__ int   g_perm[N_EDGES];
__device__ int   g_bsum[N_SB];
__device__ int   g_boff[N_SB];

// ---------------- packed f32x2 helpers ----------------
__device__ __forceinline__ ull pack2(float lo, float hi) {
    ull r;
    asm("mov.b64 %0, {%1, %2};" : "=l"(r) : "f"(lo), "f"(hi));
    return r;
}
__device__ __forceinline__ ull fma2(ull a, ull b, ull c) {
    ull d;
    asm("fma.rn.f32x2 %0, %1, %2, %3;" : "=l"(d) : "l"(a), "l"(b), "l"(c));
    return d;
}
__device__ __forceinline__ void unpack2(ull v, float& lo, float& hi) {
    asm("mov.b64 {%0, %1}, %2;" : "=f"(lo), "=f"(hi) : "l"(v));
}

// ---------------- kernels ----------------

// Transpose a DxD matrix: wt[k*D + c] = w[c*D + k]. 4 matrices.
__global__ void transpose_w_kernel(const float* __restrict__ w0,
                                   const float* __restrict__ w1,
                                   const float* __restrict__ w2,
                                   const float* __restrict__ w3,
                                   float* __restrict__ wt) {
    int i = blockIdx.x * blockDim.x + threadIdx.x;   // 0 .. 4*D*D-1
    if (i >= 4 * D * D) return;
    int m = i / (D * D);
    int r = (i % (D * D)) / D;   // source row c
    int k = i % D;               // source col k
    const float* w = (m == 0) ? w0 : (m == 1) ? w1 : (m == 2) ? w2 : w3;
    wt[m * D * D + k * D + r] = w[r * D + k];
}

// Sum of 4 embedding lookups + LayerNorm. One block (128 threads) per node.
__global__ void embed_ln_kernel(const int* __restrict__ x,
                                const float* __restrict__ syn,
                                const float* __restrict__ lem,
                                const float* __restrict__ pos,
                                const float* __restrict__ sen,
                                const float* __restrict__ g,
                                const float* __restrict__ b,
                                float* __restrict__ out) {
    int node = blockIdx.x;
    int t = threadIdx.x;
    int4 xi = ((const int4*)x)[node];  // cols 0..3
    float f = syn[(long)xi.x * D + t] + pos[(long)xi.y * D + t] +
              sen[(long)xi.z * D + t] + lem[(long)xi.w * D + t];

    __shared__ float red1[4];
    __shared__ float red2[4];
    int w = t >> 5, l = t & 31;

    float s = f;
    #pragma unroll
    for (int o = 16; o > 0; o >>= 1) s += __shfl_xor_sync(0xffffffffu, s, o);
    if (l == 0) red1[w] = s;
    __syncthreads();
    float mu = (red1[0] + red1[1] + red1[2] + red1[3]) * (1.0f / D);

    float d = f - mu;
    float v = d * d;
    #pragma unroll
    for (int o = 16; o > 0; o >>= 1) v += __shfl_xor_sync(0xffffffffu, v, o);
    if (l == 0) red2[w] = v;
    __syncthreads();
    float var = (red2[0] + red2[1] + red2[2] + red2[3]) * (1.0f / D);

    out[node * D + t] = d * rsqrtf(var + LN_EPS) * g[t] + b[t];
}

// In-degree count (int).
__global__ void count_kernel(const int* __restrict__ ei, int* __restrict__ deg) {
    int e = blockIdx.x * blockDim.x + threadIdx.x;
    if (e < N_EDGES) atomicAdd(&deg[ei[N_EDGES + e]], 1);
}

// Phase 1: per-block sum of 256 degrees.
__global__ __launch_bounds__(SCAN_B)
void block_sum_kernel(const int* __restrict__ deg, int* __restrict__ bsum) {
    __shared__ int ws[8];
    int node = blockIdx.x * SCAN_B + threadIdx.x;
    int d = (node < N_NODES) ? deg[node] : 0;
    int s = d;
    #pragma unroll
    for (int o = 16; o > 0; o >>= 1) s += __shfl_xor_sync(0xffffffffu, s, o);
    int w = threadIdx.x >> 5, l = threadIdx.x & 31;
    if (l == 0) ws[w] = s;
    __syncthreads();
    if (threadIdx.x == 0) {
        int tot = 0;
        #pragma unroll
        for (int i = 0; i < 8; i++) tot += ws[i];
        bsum[blockIdx.x] = tot;
    }
}

// Phase 2: exclusive scan of N_SB block sums. One block of 256 threads.
__global__ __launch_bounds__(256)
void scan_bsums_kernel(const int* __restrict__ bsum, int* __restrict__ boff) {
    __shared__ int sm[256];
    int t = threadIdx.x;
    int v = (t < N_SB) ? bsum[t] : 0;
    sm[t] = v;
    __syncthreads();
    for (int o = 1; o < 256; o <<= 1) {
        int u = (t >= o) ? sm[t - o] : 0;
        __syncthreads();
        sm[t] += u;
        __syncthreads();
    }
    if (t < N_SB) boff[t] = sm[t] - v;  // exclusive
}

// Phase 3: per-block exclusive scan + base offset -> row, cursor, invd.
__global__ __launch_bounds__(SCAN_B)
void expand_kernel(const int* __restrict__ deg,
                   const int* __restrict__ boff,
                   int* __restrict__ row,
                   int* __restrict__ cursor,
                   float* __restrict__ invd) {
    __shared__ int ws[8];
    __shared__ int wo[8];
    int t = threadIdx.x;
    int node = blockIdx.x * SCAN_B + t;
    int d = (node < N_NODES) ? deg[node] : 0;

    int incl = d;
    int l = t & 31, w = t >> 5;
    #pragma unroll
    for (int o = 1; o < 32; o <<= 1) {
        int u = __shfl_up_sync(0xffffffffu, incl, o);
        if (l >= o) incl += u;
    }
    if (l == 31) ws[w] = incl;
    __syncthreads();
    if (t == 0) {
        int run = 0;
        #pragma unroll
        for (int i = 0; i < 8; i++) { wo[i] = run; run += ws[i]; }
    }
    __syncthreads();

    if (node < N_NODES) {
        int excl = boff[blockIdx.x] + wo[w] + incl - d;
        row[node] = excl;
        cursor[node] = excl;
        invd[node] = 1.0f / fmaxf((float)d, 1.0f);
    }
    if (node == 0) row[N_NODES] = N_EDGES;
}

// Fill permutation: for each edge, place src into dst's CSR segment.
__global__ void build_perm_kernel(const int* __restrict__ ei,
                                  int* __restrict__ cursor,
                                  int* __restrict__ perm) {
    int e = blockIdx.x * blockDim.x + threadIdx.x;
    if (e >= N_EDGES) return;
    int dst = ei[N_EDGES + e];
    int pos = atomicAdd(&cursor[dst], 1);
    perm[pos] = ei[e];
}

// Mean-aggregate via CSR gather. One warp per node; lane = float4 chunk.
__global__ __launch_bounds__(256)
void gather_agg_kernel(const float* __restrict__ h,
                       const int* __restrict__ row,
                       const int* __restrict__ perm,
                       const float* __restrict__ invd,
                       float* __restrict__ agg) {
    int node = blockIdx.x * 8 + (threadIdx.x >> 5);
    int lane = threadIdx.x & 31;
    if (node >= N_NODES) return;
    int beg = row[node];
    int end = row[node + 1];

    float4 acc = make_float4(0.f, 0.f, 0.f, 0.f);
    for (int j = beg; j < end; j += 32) {
        int nj = min(32, end - j);
        int s = (j + lane < end) ? __ldg(&perm[j + lane]) : 0;
        int k = 0;
        for (; k + 8 <= nj; k += 8) {
            int s0 = __shfl_sync(0xffffffffu, s, k);
            int s1 = __shfl_sync(0xffffffffu, s, k + 1);
            int s2 = __shfl_sync(0xffffffffu, s, k + 2);
            int s3 = __shfl_sync(0xffffffffu, s, k + 3);
            int s4 = __shfl_sync(0xffffffffu, s, k + 4);
            int s5 = __shfl_sync(0xffffffffu, s, k + 5);
            int s6 = __shfl_sync(0xffffffffu, s, k + 6);
            int s7 = __shfl_sync(0xffffffffu, s, k + 7);
            float4 v0 = ((const float4*)h)[s0 * D4 + lane];
            float4 v1 = ((const float4*)h)[s1 * D4 + lane];
            float4 v2 = ((const float4*)h)[s2 * D4 + lane];
            float4 v3 = ((const float4*)h)[s3 * D4 + lane];
            float4 v4 = ((const float4*)h)[s4 * D4 + lane];
            float4 v5 = ((const float4*)h)[s5 * D4 + lane];
            float4 v6 = ((const float4*)h)[s6 * D4 + lane];
            float4 v7 = ((const float4*)h)[s7 * D4 + lane];
            acc.x += (v0.x + v1.x) + (v2.x + v3.x) + (v4.x + v5.x) + (v6.x + v7.x);
            acc.y += (v0.y + v1.y) + (v2.y + v3.y) + (v4.y + v5.y) + (v6.y + v7.y);
            acc.z += (v0.z + v1.z) + (v2.z + v3.z) + (v4.z + v5.z) + (v6.z + v7.z);
            acc.w += (v0.w + v1.w) + (v2.w + v3.w) + (v4.w + v5.w) + (v6.w + v7.w);
        }
        for (; k < nj; k++) {
            int sk = __shfl_sync(0xffffffffu, s, k);
            float4 v = ((const float4*)h)[sk * D4 + lane];
            acc.x += v.x; acc.y += v.y; acc.z += v.z; acc.w += v.w;
        }
    }
    float iv = invd[node];
    acc.x *= iv; acc.y *= iv; acc.z *= iv; acc.w *= iv;
    ((float4*)agg)[node * D4 + lane] = acc;
}

// out[n][c] = act( agg[n] . Wl[c] + bl[c] + h[n] . Wr[c] )   (agg pre-scaled)
// Weights TRANSPOSED: WT[k][c]. Inner loop uses packed fma.rn.f32x2
// (2 fp32 FMAs per instruction; ptxas never emits it from C++).
// Block: 64 nodes x 128 cols, 256 threads, thread tile 8 nodes x 4 cols.
__global__ __launch_bounds__(256)
void combine_kernel(const float* __restrict__ agg,
                    const float* __restrict__ h,
                    const float* __restrict__ WTl,
                    const float* __restrict__ bl,
                    const float* __restrict__ WTr,
                    float* __restrict__ out,
                    int relu) {
    extern __shared__ float smem[];
    float* sa = smem;               // [TILE_N][D]
    float* sh = smem + TILE_N * D;  // [TILE_N][D]

    int n0 = blockIdx.x * TILE_N;
    int t = threadIdx.x;

    for (int i = t; i < TILE_N * D4; i += 256) {
        int r = i / D4;
        int c4 = i % D4;
        int node = n0 + r;
        float4 av = make_float4(0.f, 0.f, 0.f, 0.f);
        float4 hv = av;
        if (node < N_NODES) {
            av = ((const float4*)agg)[node * D4 + c4];
            hv = ((const float4*)h)[node * D4 + c4];
        }
        ((float4*)&sa[r * D])[c4] = av;
        ((float4*)&sh[r * D])[c4] = hv;
    }
    __syncthreads();

    int cx = (t & 31) * 4;   // column base (0..124)
    int ny = (t >> 5) * 8;   // node base within tile (0..56)

    ull acc01[8], acc23[8];  // packed accumulators: cols (0,1) and (2,3)
    #pragma unroll
    for (int n = 0; n < 8; n++) { acc01[n] = pack2(0.f, 0.f); acc23[n] = pack2(0.f, 0.f); }

    for (int k = 0; k < D; k += 4) {
        // weight pairs: wl01[kk] = (WTl[k+kk][cx], WTl[k+kk][cx+1]), etc.
        ull wl01[4], wl23[4], wr01[4], wr23[4];
        #pragma unroll
        for (int kk = 0; kk < 4; kk++) {
            float4 wl = __ldg((const float4*)&WTl[(k + kk) * D + cx]);
            float4 wr = __ldg((const float4*)&WTr[(k + kk) * D + cx]);
            wl01[kk] = pack2(wl.x, wl.y); wl23[kk] = pack2(wl.z, wl.w);
            wr01[kk] = pack2(wr.x, wr.y); wr23[kk] = pack2(wr.z, wr.w);
        }
        #pragma unroll
        for (int n = 0; n < 8; n++) {
            float4 a4 = *(const float4*)&sa[(ny + n) * D + k];  // broadcast LDS
            float4 h4 = *(const float4*)&sh[(ny + n) * D + k];
            ull aa, hh;
            aa = pack2(a4.x, a4.x); hh = pack2(h4.x, h4.x);
            acc01[n] = fma2(aa, wl01[0], acc01[n]); acc23[n] = fma2(aa, wl23[0], acc23[n]);
            acc01[n] = fma2(hh, wr01[0], acc01[n]); acc23[n] = fma2(hh, wr23[0], acc23[n]);
            aa = pack2(a4.y, a4.y); hh = pack2(h4.y, h4.y);
            acc01[n] = fma2(aa, wl01[1], acc01[n]); acc23[n] = fma2(aa, wl23[1], acc23[n]);
            acc01[n] = fma2(hh, wr01[1], acc01[n]); acc23[n] = fma2(hh, wr23[1], acc23[n]);
            aa = pack2(a4.z, a4.z); hh = pack2(h4.z, h4.z);
            acc01[n] = fma2(aa, wl01[2], acc01[n]); acc23[n] = fma2(aa, wl23[2], acc23[n]);
            acc01[n] = fma2(hh, wr01[2], acc01[n]); acc23[n] = fma2(hh, wr23[2], acc23[n]);
            aa = pack2(a4.w, a4.w); hh = pack2(h4.w, h4.w);
            acc01[n] = fma2(aa, wl01[3], acc01[n]); acc23[n] = fma2(aa, wl23[3], acc23[n]);
            acc01[n] = fma2(hh, wr01[3], acc01[n]); acc23[n] = fma2(hh, wr23[3], acc23[n]);
        }
    }

    float4 bias = __ldg((const float4*)&bl[cx]);
    #pragma unroll
    for (int n = 0; n < 8; n++) {
        int node = n0 + ny + n;
        if (node < N_NODES) {
            float4 o;
            unpack2(acc01[n], o.x, o.y);
            unpack2(acc23[n], o.z, o.w);
            o.x += bias.x; o.y += bias.y; o.z += bias.z; o.w += bias.w;
            if (relu) {
                o.x = fmaxf(o.x, 0.f);
                o.y = fmaxf(o.y, 0.f);
                o.z = fmaxf(o.z, 0.f);
                o.w = fmaxf(o.w, 0.f);
            }
            ((float4*)out)[node * D4 + (cx >> 2)] = o;
        }
    }
}

// ---------------- launch ----------------

extern "C" void kernel_launch(void* const* d_in, const int* in_sizes, int n_in,
                              void* d_out, int out_size) {
    const int*   x    = (const int*)d_in[0];
    const int*   ei   = (const int*)d_in[1];
    const float* syn  = (const float*)d_in[2];
    const float* lem  = (const float*)d_in[3];
    const float* pos  = (const float*)d_in[4];
    const float* sen  = (const float*)d_in[5];
    const float* ln_g = (const float*)d_in[6];
    const float* ln_b = (const float*)d_in[7];
    const float* Wl0  = (const float*)d_in[8];
    const float* bl0  = (const float*)d_in[9];
    const float* Wr0  = (const float*)d_in[10];
    const float* Wl1  = (const float*)d_in[11];
    const float* bl1  = (const float*)d_in[12];
    const float* Wr1  = (const float*)d_in[13];
    float* out = (float*)d_out;

    float *h0, *h1, *agg, *invd, *wt;
    int *deg, *row, *cursor, *perm, *bsum, *boff;
    cudaGetSymbolAddress((void**)&h0,     g_h0);
    cudaGetSymbolAddress((void**)&h1,     g_h1);
    cudaGetSymbolAddress((void**)&agg,    g_agg);
    cudaGetSymbolAddress((void**)&deg,    g_deg);
    cudaGetSymbolAddress((void**)&row,    g_row);
    cudaGetSymbolAddress((void**)&cursor, g_cursor);
    cudaGetSymbolAddress((void**)&invd,   g_invd);
    cudaGetSymbolAddress((void**)&perm,   g_perm);
    cudaGetSymbolAddress((void**)&bsum,   g_bsum);
    cudaGetSymbolAddress((void**)&boff,   g_boff);
    cudaGetSymbolAddress((void**)&wt,     g_WT);

    static const int smem_bytes = TILE_N * D * 4 * 2;  // 64 KB
    cudaFuncSetAttribute(combine_kernel,
                         cudaFuncAttributeMaxDynamicSharedMemorySize, smem_bytes);

    const int eblocks = (N_EDGES + 255) / 256;
    const int gather_blocks = (N_NODES + 7) / 8;
    const int combine_blocks = (N_NODES + TILE_N - 1) / TILE_N;

    // 0. transpose weights (WT[k][c])
    transpose_w_kernel<<<(4 * D * D + 255) / 256, 256>>>(Wl0, Wr0, Wl1, Wr1, wt);

    // 1. embeddings + LayerNorm -> h0
    embed_ln_kernel<<<N_NODES, 128>>>(x, syn, lem, pos, sen, ln_g, ln_b, h0);

    // 2. CSR build (parallel scan)
    cudaMemsetAsync(deg, 0, N_NODES * sizeof(int));
    count_kernel<<<eblocks, 256>>>(ei, deg);
    block_sum_kernel<<<N_SB, SCAN_B>>>(deg, bsum);
    scan_bsums_kernel<<<1, 256>>>(bsum, boff);
    expand_kernel<<<N_SB, SCAN_B>>>(deg, boff, row, cursor, invd);
    build_perm_kernel<<<eblocks, 256>>>(ei, cursor, perm);

    // 3. layer 0
    gather_agg_kernel<<<gather_blocks, 256>>>(h0, row, perm, invd, agg);
    combine_kernel<<<combine_blocks, 256, smem_bytes>>>(agg, h0,
        wt + 0 * D * D, bl0, wt + 1 * D * D, h1, 1);

    // 4. layer 1
    gather_agg_kernel<<<gather_blocks, 256>>>(h1, row, perm, invd, agg);
    combine_kernel<<<combine_blocks, 256, smem_bytes>>>(agg, h1,
        wt + 2 * D * D, bl1, wt + 3 * D * D, out, 0);
}

// round 8
// speedup vs baseline: 1.0644x; 1.0268x over previous
#include <cuda_runtime.h>
#include <cuda_bf16.h>
#include <math.h>

#define N_NODES 50000
#define N_EDGES 800000
#define D 128
#define D4 (D / 4)
#define LN_EPS 1e-12f
#define TILE_N 64
#define SCAN_B 256
#define N_SB ((N_NODES + SCAN_B - 1) / SCAN_B)   // 196

// ---------------- scratch (no allocation allowed) ----------------
__device__ __align__(16) float g_h0[N_NODES * D];
__device__ __align__(16) float g_h1[N_NODES * D];
__device__ __align__(16) float g_agg[N_NODES * D];
__device__ __align__(16) __nv_bfloat16 g_hb0[N_NODES * D];  // bf16 mirror of h0
__device__ __align__(16) __nv_bfloat16 g_hb1[N_NODES * D];  // bf16 mirror of h1
__device__ __align__(16) float g_WT[4][D * D];   // Wl0^T, Wr0^T, Wl1^T, Wr1^T (as WT[k][c])
__device__ int   g_deg[N_NODES];
__device__ int   g_row[N_NODES + 1];
__device__ int   g_cursor[N_NODES];
__device__ float g_invd[N_NODES];
__device__ int   g_perm[N_EDGES];
__device__ int   g_bsum[N_SB];
__device__ int   g_boff[N_SB];

// ---------------- kernels ----------------

// Transpose a DxD matrix: wt[k*D + c] = w[c*D + k]. 4 matrices.
__global__ void transpose_w_kernel(const float* __restrict__ w0,
                                   const float* __restrict__ w1,
                                   const float* __restrict__ w2,
                                   const float* __restrict__ w3,
                                   float* __restrict__ wt) {
    int i = blockIdx.x * blockDim.x + threadIdx.x;   // 0 .. 4*D*D-1
    if (i >= 4 * D * D) return;
    int m = i / (D * D);
    int r = (i % (D * D)) / D;   // source row c
    int k = i % D;               // source col k
    const float* w = (m == 0) ? w0 : (m == 1) ? w1 : (m == 2) ? w2 : w3;
    wt[m * D * D + k * D + r] = w[r * D + k];
}

// Sum of 4 embedding lookups + LayerNorm. One block (128 threads) per node.
// Writes fp32 h and bf16 mirror.
__global__ void embed_ln_kernel(const int* __restrict__ x,
                                const float* __restrict__ syn,
                                const float* __restrict__ lem,
                                const float* __restrict__ pos,
                                const float* __restrict__ sen,
                                const float* __restrict__ g,
                                const float* __restrict__ b,
                                float* __restrict__ out,
                                __nv_bfloat16* __restrict__ outb) {
    int node = blockIdx.x;
    int t = threadIdx.x;
    int4 xi = ((const int4*)x)[node];  // cols 0..3
    float f = syn[(long)xi.x * D + t] + pos[(long)xi.y * D + t] +
              sen[(long)xi.z * D + t] + lem[(long)xi.w * D + t];

    __shared__ float red1[4];
    __shared__ float red2[4];
    int w = t >> 5, l = t & 31;

    float s = f;
    #pragma unroll
    for (int o = 16; o > 0; o >>= 1) s += __shfl_xor_sync(0xffffffffu, s, o);
    if (l == 0) red1[w] = s;
    __syncthreads();
    float mu = (red1[0] + red1[1] + red1[2] + red1[3]) * (1.0f / D);

    float d = f - mu;
    float v = d * d;
    #pragma unroll
    for (int o = 16; o > 0; o >>= 1) v += __shfl_xor_sync(0xffffffffu, v, o);
    if (l == 0) red2[w] = v;
    __syncthreads();
    float var = (red2[0] + red2[1] + red2[2] + red2[3]) * (1.0f / D);

    float r = d * rsqrtf(var + LN_EPS) * g[t] + b[t];
    out[node * D + t] = r;
    outb[node * D + t] = __float2bfloat16(r);
}

// In-degree count (int).
__global__ void count_kernel(const int* __restrict__ ei, int* __restrict__ deg) {
    int e = blockIdx.x * blockDim.x + threadIdx.x;
    if (e < N_EDGES) atomicAdd(&deg[ei[N_EDGES + e]], 1);
}

// Phase 1: per-block sum of 256 degrees.
__global__ __launch_bounds__(SCAN_B)
void block_sum_kernel(const int* __restrict__ deg, int* __restrict__ bsum) {
    __shared__ int ws[8];
    int node = blockIdx.x * SCAN_B + threadIdx.x;
    int d = (node < N_NODES) ? deg[node] : 0;
    int s = d;
    #pragma unroll
    for (int o = 16; o > 0; o >>= 1) s += __shfl_xor_sync(0xffffffffu, s, o);
    int w = threadIdx.x >> 5, l = threadIdx.x & 31;
    if (l == 0) ws[w] = s;
    __syncthreads();
    if (threadIdx.x == 0) {
        int tot = 0;
        #pragma unroll
        for (int i = 0; i < 8; i++) tot += ws[i];
        bsum[blockIdx.x] = tot;
    }
}

// Phase 2: exclusive scan of N_SB block sums. One block of 256 threads.
__global__ __launch_bounds__(256)
void scan_bsums_kernel(const int* __restrict__ bsum, int* __restrict__ boff) {
    __shared__ int sm[256];
    int t = threadIdx.x;
    int v = (t < N_SB) ? bsum[t] : 0;
    sm[t] = v;
    __syncthreads();
    for (int o = 1; o < 256; o <<= 1) {
        int u = (t >= o) ? sm[t - o] : 0;
        __syncthreads();
        sm[t] += u;
        __syncthreads();
    }
    if (t < N_SB) boff[t] = sm[t] - v;  // exclusive
}

// Phase 3: per-block exclusive scan + base offset -> row, cursor, invd.
__global__ __launch_bounds__(SCAN_B)
void expand_kernel(const int* __restrict__ deg,
                   const int* __restrict__ boff,
                   int* __restrict__ row,
                   int* __restrict__ cursor,
                   float* __restrict__ invd) {
    __shared__ int ws[8];
    __shared__ int wo[8];
    int t = threadIdx.x;
    int node = blockIdx.x * SCAN_B + t;
    int d = (node < N_NODES) ? deg[node] : 0;

    int incl = d;
    int l = t & 31, w = t >> 5;
    #pragma unroll
    for (int o = 1; o < 32; o <<= 1) {
        int u = __shfl_up_sync(0xffffffffu, incl, o);
        if (l >= o) incl += u;
    }
    if (l == 31) ws[w] = incl;
    __syncthreads();
    if (t == 0) {
        int run = 0;
        #pragma unroll
        for (int i = 0; i < 8; i++) { wo[i] = run; run += ws[i]; }
    }
    __syncthreads();

    if (node < N_NODES) {
        int excl = boff[blockIdx.x] + wo[w] + incl - d;
        row[node] = excl;
        cursor[node] = excl;
        invd[node] = 1.0f / fmaxf((float)d, 1.0f);
    }
    if (node == 0) row[N_NODES] = N_EDGES;
}

// Fill permutation: for each edge, place src into dst's CSR segment.
__global__ void build_perm_kernel(const int* __restrict__ ei,
                                  int* __restrict__ cursor,
                                  int* __restrict__ perm) {
    int e = blockIdx.x * blockDim.x + threadIdx.x;
    if (e >= N_EDGES) return;
    int dst = ei[N_EDGES + e];
    int pos = atomicAdd(&cursor[dst], 1);
    perm[pos] = ei[e];
}

__device__ __forceinline__ void acc8_bf16(float* acc, uint4 v) {
    float2 f;
    f = __bfloat1622float2(*(const __nv_bfloat162*)&v.x); acc[0] += f.x; acc[1] += f.y;
    f = __bfloat1622float2(*(const __nv_bfloat162*)&v.y); acc[2] += f.x; acc[3] += f.y;
    f = __bfloat1622float2(*(const __nv_bfloat162*)&v.z); acc[4] += f.x; acc[5] += f.y;
    f = __bfloat1622float2(*(const __nv_bfloat162*)&v.w); acc[6] += f.x; acc[7] += f.y;
}

// Mean-aggregate via CSR gather over the bf16 mirror (fp32 accumulation).
// One warp per node. Row = 256B; half-warp per neighbor row, 2 rows per step.
// Lane l: half = l>>4, sub = l&15 covers cols [8*sub, 8*sub+8).
__global__ __launch_bounds__(256)
void gather_agg_kernel(const __nv_bfloat16* __restrict__ hb,
                       const int* __restrict__ row,
                       const int* __restrict__ perm,
                       const float* __restrict__ invd,
                       float* __restrict__ agg) {
    int node = blockIdx.x * 8 + (threadIdx.x >> 5);
    int lane = threadIdx.x & 31;
    if (node >= N_NODES) return;
    int half = lane >> 4;
    int sub = lane & 15;
    int beg = row[node];
    int end = row[node + 1];
    const uint4* hbu = (const uint4*)hb;   // 16 uint4 per row

    float acc[8];
    #pragma unroll
    for (int j = 0; j < 8; j++) acc[j] = 0.f;

    for (int j = beg; j < end; j += 32) {
        int nj = min(32, end - j);
        int s = (j + lane < end) ? __ldg(&perm[j + lane]) : 0;
        int k = 0;
        for (; k + 8 <= nj; k += 8) {   // 8 neighbors = 4 pair-steps
            int s0 = __shfl_sync(0xffffffffu, s, k + 0 + half);
            int s1 = __shfl_sync(0xffffffffu, s, k + 2 + half);
            int s2 = __shfl_sync(0xffffffffu, s, k + 4 + half);
            int s3 = __shfl_sync(0xffffffffu, s, k + 6 + half);
            uint4 v0 = hbu[s0 * 16 + sub];
            uint4 v1 = hbu[s1 * 16 + sub];
            uint4 v2 = hbu[s2 * 16 + sub];
            uint4 v3 = hbu[s3 * 16 + sub];
            acc8_bf16(acc, v0);
            acc8_bf16(acc, v1);
            acc8_bf16(acc, v2);
            acc8_bf16(acc, v3);
        }
        for (; k < nj; k += 2) {        // tail pairs (maybe odd)
            int idx = k + half;
            int sk = __shfl_sync(0xffffffffu, s, (idx < nj) ? idx : k);
            if (idx < nj) {
                uint4 v = hbu[sk * 16 + sub];
                acc8_bf16(acc, v);
            }
        }
    }

    // combine the two half-warps (different neighbor subsets, same cols)
    float iv = invd[node];
    #pragma unroll
    for (int j = 0; j < 8; j++) {
        acc[j] += __shfl_xor_sync(0xffffffffu, acc[j], 16);
        acc[j] *= iv;
    }
    if (lane < 16) {
        float4 o0 = make_float4(acc[0], acc[1], acc[2], acc[3]);
        float4 o1 = make_float4(acc[4], acc[5], acc[6], acc[7]);
        ((float4*)agg)[node * 32 + sub * 2 + 0] = o0;
        ((float4*)agg)[node * 32 + sub * 2 + 1] = o1;
    }
}

// out[n][c] = act( agg[n] . Wl[c] + bl[c] + h[n] . Wr[c] )   (agg pre-scaled)
// Weights TRANSPOSED: WT[k][c]. Optionally writes bf16 mirror of out.
// Block: 64 nodes x 128 cols, 256 threads, thread tile 8 nodes x 4 cols.
__global__ __launch_bounds__(256)
void combine_kernel(const float* __restrict__ agg,
                    const float* __restrict__ h,
                    const float* __restrict__ WTl,
                    const float* __restrict__ bl,
                    const float* __restrict__ WTr,
                    float* __restrict__ out,
                    __nv_bfloat16* __restrict__ outb,   // may be null
                    int relu) {
    extern __shared__ float smem[];
    float* sa = smem;               // [TILE_N][D]
    float* sh = smem + TILE_N * D;  // [TILE_N][D]

    int n0 = blockIdx.x * TILE_N;
    int t = threadIdx.x;

    for (int i = t; i < TILE_N * D4; i += 256) {
        int r = i / D4;
        int c4 = i % D4;
        int node = n0 + r;
        float4 av = make_float4(0.f, 0.f, 0.f, 0.f);
        float4 hv = av;
        if (node < N_NODES) {
            av = ((const float4*)agg)[node * D4 + c4];
            hv = ((const float4*)h)[node * D4 + c4];
        }
        ((float4*)&sa[r * D])[c4] = av;
        ((float4*)&sh[r * D])[c4] = hv;
    }
    __syncthreads();

    int cx = (t & 31) * 4;   // column base (0..124)
    int ny = (t >> 5) * 8;   // node base within tile (0..56)

    float acc[8][4];
    #pragma unroll
    for (int n = 0; n < 8; n++)
        #pragma unroll
        for (int j = 0; j < 4; j++) acc[n][j] = 0.f;

    for (int k = 0; k < D; k += 4) {
        float4 wl[4], wr[4];
        #pragma unroll
        for (int kk = 0; kk < 4; kk++) {
            wl[kk] = __ldg((const float4*)&WTl[(k + kk) * D + cx]);
            wr[kk] = __ldg((const float4*)&WTr[(k + kk) * D + cx]);
        }
        #pragma unroll
        for (int n = 0; n < 8; n++) {
            float4 a4 = *(const float4*)&sa[(ny + n) * D + k];  // broadcast LDS
            float4 h4 = *(const float4*)&sh[(ny + n) * D + k];
            #pragma unroll
            for (int j = 0; j < 4; j++) {
                float r = acc[n][j];
                r = fmaf(a4.x, ((const float*)&wl[0])[j], r);
                r = fmaf(a4.y, ((const float*)&wl[1])[j], r);
                r = fmaf(a4.z, ((const float*)&wl[2])[j], r);
                r = fmaf(a4.w, ((const float*)&wl[3])[j], r);
                r = fmaf(h4.x, ((const float*)&wr[0])[j], r);
                r = fmaf(h4.y, ((const float*)&wr[1])[j], r);
                r = fmaf(h4.z, ((const float*)&wr[2])[j], r);
                r = fmaf(h4.w, ((const float*)&wr[3])[j], r);
                acc[n][j] = r;
            }
        }
    }

    float4 bias = __ldg((const float4*)&bl[cx]);
    #pragma unroll
    for (int n = 0; n < 8; n++) {
        int node = n0 + ny + n;
        if (node < N_NODES) {
            float4 o;
            o.x = acc[n][0] + bias.x;
            o.y = acc[n][1] + bias.y;
            o.z = acc[n][2] + bias.z;
            o.w = acc[n][3] + bias.w;
            if (relu) {
                o.x = fmaxf(o.x, 0.f);
                o.y = fmaxf(o.y, 0.f);
                o.z = fmaxf(o.z, 0.f);
                o.w = fmaxf(o.w, 0.f);
            }
            ((float4*)out)[node * D4 + (cx >> 2)] = o;
            if (outb) {
                __nv_bfloat162 p0 = __floats2bfloat162_rn(o.x, o.y);
                __nv_bfloat162 p1 = __floats2bfloat162_rn(o.z, o.w);
                uint2 u;
                u.x = *(unsigned*)&p0;
                u.y = *(unsigned*)&p1;
                *(uint2*)&outb[node * D + cx] = u;
            }
        }
    }
}

// ---------------- launch ----------------

extern "C" void kernel_launch(void* const* d_in, const int* in_sizes, int n_in,
                              void* d_out, int out_size) {
    const int*   x    = (const int*)d_in[0];
    const int*   ei   = (const int*)d_in[1];
    const float* syn  = (const float*)d_in[2];
    const float* lem  = (const float*)d_in[3];
    const float* pos  = (const float*)d_in[4];
    const float* sen  = (const float*)d_in[5];
    const float* ln_g = (const float*)d_in[6];
    const float* ln_b = (const float*)d_in[7];
    const float* Wl0  = (const float*)d_in[8];
    const float* bl0  = (const float*)d_in[9];
    const float* Wr0  = (const float*)d_in[10];
    const float* Wl1  = (const float*)d_in[11];
    const float* bl1  = (const float*)d_in[12];
    const float* Wr1  = (const float*)d_in[13];
    float* out = (float*)d_out;

    float *h0, *h1, *agg, *invd, *wt;
    __nv_bfloat16 *hb0, *hb1;
    int *deg, *row, *cursor, *perm, *bsum, *boff;
    cudaGetSymbolAddress((void**)&h0,     g_h0);
    cudaGetSymbolAddress((void**)&h1,     g_h1);
    cudaGetSymbolAddress((void**)&agg,    g_agg);
    cudaGetSymbolAddress((void**)&hb0,    g_hb0);
    cudaGetSymbolAddress((void**)&hb1,    g_hb1);
    cudaGetSymbolAddress((void**)&deg,    g_deg);
    cudaGetSymbolAddress((void**)&row,    g_row);
    cudaGetSymbolAddress((void**)&cursor, g_cursor);
    cudaGetSymbolAddress((void**)&invd,   g_invd);
    cudaGetSymbolAddress((void**)&perm,   g_perm);
    cudaGetSymbolAddress((void**)&bsum,   g_bsum);
    cudaGetSymbolAddress((void**)&boff,   g_boff);
    cudaGetSymbolAddress((void**)&wt,     g_WT);

    static const int smem_bytes = TILE_N * D * 4 * 2;  // 64 KB
    cudaFuncSetAttribute(combine_kernel,
                         cudaFuncAttributeMaxDynamicSharedMemorySize, smem_bytes);

    const int eblocks = (N_EDGES + 255) / 256;
    const int gather_blocks = (N_NODES + 7) / 8;
    const int combine_blocks = (N_NODES + TILE_N - 1) / TILE_N;

    // 0. transpose weights (WT[k][c])
    transpose_w_kernel<<<(4 * D * D + 255) / 256, 256>>>(Wl0, Wr0, Wl1, Wr1, wt);

    // 1. embeddings + LayerNorm -> h0 (fp32) + hb0 (bf16)
    embed_ln_kernel<<<N_NODES, 128>>>(x, syn, lem, pos, sen, ln_g, ln_b, h0, hb0);

    // 2. CSR build (parallel scan)
    cudaMemsetAsync(deg, 0, N_NODES * sizeof(int));
    count_kernel<<<eblocks, 256>>>(ei, deg);
    block_sum_kernel<<<N_SB, SCAN_B>>>(deg, bsum);
    scan_bsums_kernel<<<1, 256>>>(bsum, boff);
    expand_kernel<<<N_SB, SCAN_B>>>(deg, boff, row, cursor, invd);
    build_perm_kernel<<<eblocks, 256>>>(ei, cursor, perm);

    // 3. layer 0
    gather_agg_kernel<<<gather_blocks, 256>>>(hb0, row, perm, invd, agg);
    combine_kernel<<<combine_blocks, 256, smem_bytes>>>(agg, h0,
        wt + 0 * D * D, bl0, wt + 1 * D * D, h1, hb1, 1);

    // 4. layer 1
    gather_agg_kernel<<<gather_blocks, 256>>>(hb1, row, perm, invd, agg);
    combine_kernel<<<combine_blocks, 256, smem_bytes>>>(agg, h1,
        wt + 2 * D * D, bl1, wt + 3 * D * D, out, (__nv_bfloat16*)0, 0);
}